// round 16
// baseline (speedup 1.0000x reference)
#include <cuda_runtime.h>
#include <cuda_bf16.h>
#include <cuda_fp16.h>
#include <cstdint>

#define NN 100000
#define EE 1600000
#define HD 128
#define NC 8
#define EPS_BN 1e-5f
#define SLOPE 0.01f

#define NTILES ((NN + 127) / 128)                    // 782
#define NET_GRID 148
#define NET_TB 1024
#define CSR_GRID 148
#define CSR_TB 1024

#define LDA 136
#define ABUF_SZ (128 * LDA * 2)             // 34816
#define BUF_PAIR (2 * ABUF_SZ)              // 69632
#define OFF_W_HI (2 * BUF_PAIR)             // 139264
#define OFF_W_LO (OFF_W_HI + ABUF_SZ)       // 174080
#define OFF_STATS (OFF_W_LO + ABUF_SZ)      // 208896
#define OFF_WC   (OFF_STATS + 1024)         // 209920
#define SM_TOTAL (OFF_WC + 4096)            // 214016

// ---- device scratch ----
__device__ __nv_bfloat16 g_Ah[(size_t)NN * HD];
__device__ __nv_bfloat16 g_Al[(size_t)NN * HD];
__device__ __half g_Xh[(size_t)NN * HD];
__device__ __half g_Bh[(size_t)NN * HD];
__device__ float g_outnorm[NN];
__device__ float g_innorm[NN];
__device__ int   g_srccnt[NN];
__device__ int   g_dstcnt[NN];
__device__ int   g_excl[NN];
__device__ int   g_blksum[CSR_GRID];
__device__ int   g_rowptr[NN + 1];
__device__ int   g_cursor[NN];
__device__ int   g_esrc[EE];
__device__ float g_stats1[2 * HD];
__device__ float g_stats2[2 * HD];
__device__ __nv_bfloat16 g_Wtb[8 * 16384];
__device__ unsigned g_bar[8];
__device__ unsigned g_exit;
__device__ unsigned g_nbar[8];
__device__ unsigned g_nexit;

// ==================== persistent CSR mega-kernel ============================
__device__ __forceinline__ void grid_barrier_csr(int k) {
    __syncthreads();
    if (threadIdx.x == 0) {
        __threadfence();
        atomicAdd(&g_bar[k], 1u);
        while (atomicAdd(&g_bar[k], 0u) < (unsigned)CSR_GRID) {}
        __threadfence();
    }
    __syncthreads();
}

__global__ void __launch_bounds__(CSR_TB, 1)
csr_mega_kernel(const int* __restrict__ src, const int* __restrict__ dst,
                const float* __restrict__ node_feat,
                int* srccnt, int* dstcnt, float* outnorm, float* innorm,
                int* excl, int* blksum, int* rowptr, int* cursor, int* esrc,
                __half* xh, float* stats1, float* stats2) {
    int tid = threadIdx.x;
    int gtid = blockIdx.x * CSR_TB + tid;
    const int nth = CSR_GRID * CSR_TB;

    for (int i = gtid; i < NN; i += nth) { srccnt[i] = 0; dstcnt[i] = 0; }
    if (gtid < 2 * HD) { stats1[gtid] = 0.f; stats2[gtid] = 0.f; }
    grid_barrier_csr(0);

    for (int e = gtid; e < EE; e += nth) {
        atomicAdd(&srccnt[src[e]], 1);
        atomicAdd(&dstcnt[dst[e]], 1);
    }
    grid_barrier_csr(1);

    for (int i = gtid; i < NN; i += nth) {
        outnorm[i] = rsqrtf(fmaxf((float)srccnt[i], 1.f));
        innorm[i]  = rsqrtf(fmaxf((float)dstcnt[i], 1.f));
    }
    {
        __shared__ int sh[CSR_TB];
        int i = gtid;
        int v = (i < NN) ? dstcnt[i] : 0;
        sh[tid] = v;
        __syncthreads();
        for (int off = 1; off < CSR_TB; off <<= 1) {
            int t = (tid >= off) ? sh[tid - off] : 0;
            __syncthreads();
            sh[tid] += t;
            __syncthreads();
        }
        if (i < NN) excl[i] = sh[tid] - v;
        if (tid == CSR_TB - 1) blksum[blockIdx.x] = sh[tid];
    }
    grid_barrier_csr(2);

    if (blockIdx.x == 0) {
        __shared__ int sb2[256];
        int v = (tid < CSR_GRID) ? blksum[tid] : 0;
        if (tid < 256) sb2[tid] = v;
        __syncthreads();
        for (int off = 1; off < 256; off <<= 1) {
            int t = (tid >= off && tid < 256) ? sb2[tid - off] : 0;
            __syncthreads();
            if (tid < 256) sb2[tid] += t;
            __syncthreads();
        }
        if (tid < CSR_GRID) blksum[tid] = sb2[tid] - v;
    }
    grid_barrier_csr(3);

    for (int i = gtid; i < NN; i += nth) {
        int r = excl[i] + blksum[i >> 10];
        rowptr[i] = r;
        cursor[i] = r;
    }
    for (long long i = gtid; i < (long long)NN * 64; i += nth) {
        int node = (int)(i >> 6);
        float w = outnorm[node];
        float2 v = ((const float2*)node_feat)[i];
        ((__half2*)xh)[i] = __floats2half2_rn(v.x * w, v.y * w);
    }
    if (gtid == 0) rowptr[NN] = EE;
    grid_barrier_csr(4);

    for (int e = gtid; e < EE; e += nth) {
        int p = atomicAdd(&cursor[dst[e]], 1);
        esrc[p] = src[e];
    }

    __syncthreads();
    if (tid == 0) {
        __threadfence();
        unsigned v = atomicAdd(&g_exit, 1u);
        if (v == CSR_GRID - 1) {
            #pragma unroll
            for (int k = 0; k < 8; k++) atomicExch(&g_bar[k], 0u);
            atomicExch(&g_exit, 0u);
            __threadfence();
        }
    }
}

// ===================== weight prep: W^T hi/lo bf16 ==========================
__global__ void prep_w_kernel(const float* __restrict__ Wa, const float* __restrict__ Wb,
                              const float* __restrict__ Wc_, const float* __restrict__ Wd,
                              __nv_bfloat16* __restrict__ Wt) {
    const float* W = (blockIdx.x == 0) ? Wa : (blockIdx.x == 1) ? Wb : (blockIdx.x == 2) ? Wc_ : Wd;
    __nv_bfloat16* hi_t = Wt + (size_t)blockIdx.x * 2 * 16384;
    __nv_bfloat16* lo_t = hi_t + 16384;
    for (int idx = threadIdx.x; idx < HD * HD; idx += 256) {
        int k = idx >> 7, n = idx & 127;
        float w = W[idx];
        __nv_bfloat16 h = __float2bfloat16_rn(w);
        float r = w - __bfloat162float(h);
        hi_t[n * HD + k] = h;
        lo_t[n * HD + k] = __float2bfloat16_rn(r);
    }
}

// ========================== persistent network kernel =======================
__device__ __forceinline__ uint32_t smem_u32(const void* p) {
    uint32_t a;
    asm("{ .reg .u64 t; cvta.to.shared.u64 t, %1; cvt.u32.u64 %0, t; }" : "=r"(a) : "l"(p));
    return a;
}
#define LDSM_X4(r0, r1, r2, r3, a) \
    asm volatile("ldmatrix.sync.aligned.m8n8.x4.shared.b16 {%0,%1,%2,%3}, [%4];" \
        : "=r"(r0), "=r"(r1), "=r"(r2), "=r"(r3) : "r"(a))
#define LDSM_X2(r0, r1, a) \
    asm volatile("ldmatrix.sync.aligned.m8n8.x2.shared.b16 {%0,%1}, [%2];" \
        : "=r"(r0), "=r"(r1) : "r"(a))
#define MMA16816(c, A0, A1, A2, A3, B0, B1) \
    asm volatile("mma.sync.aligned.m16n8k16.row.col.f32.bf16.bf16.f32 " \
        "{%0,%1,%2,%3}, {%4,%5,%6,%7}, {%8,%9}, {%0,%1,%2,%3};" \
        : "+f"((c)[0]), "+f"((c)[1]), "+f"((c)[2]), "+f"((c)[3]) \
        : "r"(A0), "r"(A1), "r"(A2), "r"(A3), "r"(B0), "r"(B1))
#define CP_ASYNC16(dst, src, sz) \
    asm volatile("cp.async.cg.shared.global [%0], [%1], 16, %2;" :: "r"(dst), "l"(src), "r"(sz))
#define CP_COMMIT() asm volatile("cp.async.commit_group;" ::: "memory")
#define CP_WAIT0()  asm volatile("cp.async.wait_group 0;" ::: "memory")

__device__ __forceinline__ void grid_barrier_net(int k) {
    __syncthreads();
    if (threadIdx.x == 0) {
        __threadfence();
        atomicAdd(&g_nbar[k], 1u);
        while (atomicAdd(&g_nbar[k], 0u) < (unsigned)NET_GRID) {}
        __threadfence();
    }
    __syncthreads();
}

// --- agg phase: warp-strided over nodes; optional BN(stats)+lrelu on input ---
__device__ void agg_phase(const __half* __restrict__ x,
                          const float* __restrict__ statsrc,   // null or g_stats*
                          const float* __restrict__ gamma,
                          const float* __restrict__ beta,
                          const int* __restrict__ rowptr,
                          const int* __restrict__ esrc,
                          const float* __restrict__ outnorm,
                          const float* __restrict__ innorm,
                          __nv_bfloat16* __restrict__ Ahi,
                          __nv_bfloat16* __restrict__ Alo) {
    int wid = threadIdx.x >> 5;
    int lane = threadIdx.x & 31;
    const uint2* x2 = (const uint2*)x;

    float4 sc, bi;
    if (statsrc) {
        #pragma unroll
        for (int k = 0; k < 4; k++) {
            int c = lane * 4 + k;
            float mean = statsrc[c] * (1.f / NN);
            float var = statsrc[HD + c] * (1.f / NN) - mean * mean;
            float r = rsqrtf(var + EPS_BN) * gamma[c];
            ((float*)&sc)[k] = r;
            ((float*)&bi)[k] = beta[c] - mean * r;
        }
    }

    for (int node = blockIdx.x * 32 + wid; node < NN; node += NET_GRID * 32) {
        int beg = rowptr[node], end = rowptr[node + 1];
        float4 acc = make_float4(0.f, 0.f, 0.f, 0.f);

        if (statsrc) {
            int j = beg;
            for (; j + 1 < end; j += 2) {
                int s0 = esrc[j], s1 = esrc[j + 1];
                float w0 = outnorm[s0], w1 = outnorm[s1];
                uint2 u0 = x2[(size_t)s0 * 32 + lane];
                uint2 u1 = x2[(size_t)s1 * 32 + lane];
                float2 a0 = __half22float2(*(__half2*)&u0.x);
                float2 a1 = __half22float2(*(__half2*)&u0.y);
                float2 c0 = __half22float2(*(__half2*)&u1.x);
                float2 c1 = __half22float2(*(__half2*)&u1.y);
                float t0, t1;
                t0 = fmaf(a0.x, sc.x, bi.x); t0 = t0 >= 0.f ? t0 : SLOPE * t0;
                t1 = fmaf(c0.x, sc.x, bi.x); t1 = t1 >= 0.f ? t1 : SLOPE * t1;
                acc.x += w0 * t0 + w1 * t1;
                t0 = fmaf(a0.y, sc.y, bi.y); t0 = t0 >= 0.f ? t0 : SLOPE * t0;
                t1 = fmaf(c0.y, sc.y, bi.y); t1 = t1 >= 0.f ? t1 : SLOPE * t1;
                acc.y += w0 * t0 + w1 * t1;
                t0 = fmaf(a1.x, sc.z, bi.z); t0 = t0 >= 0.f ? t0 : SLOPE * t0;
                t1 = fmaf(c1.x, sc.z, bi.z); t1 = t1 >= 0.f ? t1 : SLOPE * t1;
                acc.z += w0 * t0 + w1 * t1;
                t0 = fmaf(a1.y, sc.w, bi.w); t0 = t0 >= 0.f ? t0 : SLOPE * t0;
                t1 = fmaf(c1.y, sc.w, bi.w); t1 = t1 >= 0.f ? t1 : SLOPE * t1;
                acc.w += w0 * t0 + w1 * t1;
            }
            if (j < end) {
                int s = esrc[j];
                float w = outnorm[s];
                uint2 u = x2[(size_t)s * 32 + lane];
                float2 a0 = __half22float2(*(__half2*)&u.x);
                float2 a1 = __half22float2(*(__half2*)&u.y);
                float t;
                t = fmaf(a0.x, sc.x, bi.x); t = t >= 0.f ? t : SLOPE * t; acc.x += w * t;
                t = fmaf(a0.y, sc.y, bi.y); t = t >= 0.f ? t : SLOPE * t; acc.y += w * t;
                t = fmaf(a1.x, sc.z, bi.z); t = t >= 0.f ? t : SLOPE * t; acc.z += w * t;
                t = fmaf(a1.y, sc.w, bi.w); t = t >= 0.f ? t : SLOPE * t; acc.w += w * t;
            }
        } else {
            int j = beg;
            for (; j + 3 < end; j += 4) {
                int s0 = esrc[j], s1 = esrc[j + 1], s2 = esrc[j + 2], s3 = esrc[j + 3];
                uint2 u0 = x2[(size_t)s0 * 32 + lane];
                uint2 u1 = x2[(size_t)s1 * 32 + lane];
                uint2 u2 = x2[(size_t)s2 * 32 + lane];
                uint2 u3 = x2[(size_t)s3 * 32 + lane];
                float2 a0 = __half22float2(*(__half2*)&u0.x), a1 = __half22float2(*(__half2*)&u0.y);
                float2 b0 = __half22float2(*(__half2*)&u1.x), b1 = __half22float2(*(__half2*)&u1.y);
                float2 c0 = __half22float2(*(__half2*)&u2.x), c1 = __half22float2(*(__half2*)&u2.y);
                float2 d0 = __half22float2(*(__half2*)&u3.x), d1 = __half22float2(*(__half2*)&u3.y);
                acc.x += a0.x + b0.x + c0.x + d0.x;
                acc.y += a0.y + b0.y + c0.y + d0.y;
                acc.z += a1.x + b1.x + c1.x + d1.x;
                acc.w += a1.y + b1.y + c1.y + d1.y;
            }
            for (; j < end; j++) {
                int s = esrc[j];
                uint2 u = x2[(size_t)s * 32 + lane];
                float2 a0 = __half22float2(*(__half2*)&u.x);
                float2 a1 = __half22float2(*(__half2*)&u.y);
                acc.x += a0.x; acc.y += a0.y; acc.z += a1.x; acc.w += a1.y;
            }
        }
        float in = innorm[node];
        acc.x *= in; acc.y *= in; acc.z *= in; acc.w *= in;

        __nv_bfloat16 h0 = __float2bfloat16_rn(acc.x);
        __nv_bfloat16 h1 = __float2bfloat16_rn(acc.y);
        __nv_bfloat16 h2 = __float2bfloat16_rn(acc.z);
        __nv_bfloat16 h3 = __float2bfloat16_rn(acc.w);
        __nv_bfloat162 ph0 = {h0, h1}, ph1 = {h2, h3};
        __nv_bfloat162 pl0 = {__float2bfloat16_rn(acc.x - __bfloat162float(h0)),
                              __float2bfloat16_rn(acc.y - __bfloat162float(h1))};
        __nv_bfloat162 pl1 = {__float2bfloat16_rn(acc.z - __bfloat162float(h2)),
                              __float2bfloat16_rn(acc.w - __bfloat162float(h3))};
        ((uint2*)(Ahi + (size_t)node * HD))[lane] = make_uint2(*(uint32_t*)&ph0, *(uint32_t*)&ph1);
        ((uint2*)(Alo + (size_t)node * HD))[lane] = make_uint2(*(uint32_t*)&pl0, *(uint32_t*)&pl1);
    }
}

// --- gemm phase: R15-proven pipelined mma loop ---
__device__ void gemm_phase(char* smem, uint32_t sbase,
                           const __nv_bfloat16* __restrict__ Ahi,
                           const __nv_bfloat16* __restrict__ Alo,
                           const __nv_bfloat16* __restrict__ Wt_hi,
                           const __nv_bfloat16* __restrict__ Wt_lo,
                           const float* __restrict__ bvec,
                           __half* __restrict__ out, int act,
                           float* __restrict__ stats,
                           const float* __restrict__ prenorm,
                           const float* __restrict__ Wcls,
                           const float* __restrict__ bcls,
                           float* __restrict__ cls_out) {
    float* s_stats = (float*)(smem + OFF_STATS);
    int tid = threadIdx.x;
    int wid = tid >> 5;
    int lane = tid & 31;

    {
        const uint32_t* wh = (const uint32_t*)Wt_hi;
        const uint32_t* wl = (const uint32_t*)Wt_lo;
        #pragma unroll
        for (int i = tid; i < 8192; i += NET_TB) {
            int n = i >> 6, kp = i & 63;
            *(uint32_t*)(smem + OFF_W_HI + n * (LDA * 2) + kp * 4) = wh[i];
            *(uint32_t*)(smem + OFF_W_LO + n * (LDA * 2) + kp * 4) = wl[i];
        }
    }
    if (stats && tid < 256) s_stats[tid] = 0.f;
    if (Wcls) {
        float* s_wc = (float*)(smem + OFF_WC);
        for (int i = tid; i < HD * NC; i += NET_TB) s_wc[i] = __ldg(&Wcls[i]);
    }

    int warp_m = wid >> 3;
    int warp_n = wid & 7;
    int sub = lane >> 3, r8 = lane & 7;
    int arow = warp_m * 32 + (sub & 1) * 8 + r8;
    int akoff = (sub >> 1) * 8;
    uint32_t relAh0 = (uint32_t)(arow * LDA + akoff) * 2;
    uint32_t relAh1 = relAh0 + 16 * LDA * 2;
    int bl = lane & 15;
    int brow = warp_n * 16 + (bl & 7);
    int bkoff = (bl >> 3) * 8;
    uint32_t aBh = sbase + OFF_W_HI + (brow * LDA + bkoff) * 2;
    uint32_t aBl = aBh + (OFF_W_LO - OFF_W_HI);
    int gid = lane >> 2, tig = lane & 3;

    int pr = tid >> 3;
    int pq = tid & 7;
    uint32_t pdst_rel = (uint32_t)(pr * LDA + pq * 16) * 2;

    {
        int grow = blockIdx.x * 128 + pr;
        uint32_t sz = (grow < NN) ? 16u : 0u;
        const char* sh = (const char*)(Ahi + (size_t)grow * HD + pq * 16);
        const char* sl = (const char*)(Alo + (size_t)grow * HD + pq * 16);
        uint32_t dh = sbase + pdst_rel;
        uint32_t dl = dh + ABUF_SZ;
        #pragma unroll
        for (int q = 0; q < 2; q++) {
            CP_ASYNC16(dh + q * 16, sh + q * 16, sz);
            CP_ASYNC16(dl + q * 16, sl + q * 16, sz);
        }
    }
    CP_COMMIT();
    __syncthreads();

    int cur = 0;
    for (int tile = blockIdx.x; tile < NTILES; tile += NET_GRID) {
        int block_row = tile * 128;
        int next = tile + NET_GRID;

        CP_WAIT0();
        __syncthreads();

        if (next < NTILES) {
            int grow = next * 128 + pr;
            uint32_t sz = (grow < NN) ? 16u : 0u;
            const char* sh = (const char*)(Ahi + (size_t)grow * HD + pq * 16);
            const char* sl = (const char*)(Alo + (size_t)grow * HD + pq * 16);
            uint32_t dh = sbase + (cur ^ 1) * BUF_PAIR + pdst_rel;
            uint32_t dl = dh + ABUF_SZ;
            #pragma unroll
            for (int q = 0; q < 2; q++) {
                CP_ASYNC16(dh + q * 16, sh + q * 16, sz);
                CP_ASYNC16(dl + q * 16, sl + q * 16, sz);
            }
        }
        CP_COMMIT();

        uint32_t bufb = sbase + cur * BUF_PAIR;
        uint32_t aAh0 = bufb + relAh0;
        uint32_t aAh1 = bufb + relAh1;
        uint32_t aAl0 = aAh0 + ABUF_SZ;
        uint32_t aAl1 = aAh1 + ABUF_SZ;

        float acc[2][2][4];
        #pragma unroll
        for (int m = 0; m < 2; m++)
            #pragma unroll
            for (int n = 0; n < 2; n++)
                #pragma unroll
                for (int q = 0; q < 4; q++) acc[m][n][q] = 0.f;

        #pragma unroll
        for (int ks = 0; ks < 8; ks++) {
            uint32_t ah[2][4], al[2][4];
            LDSM_X4(ah[0][0], ah[0][1], ah[0][2], ah[0][3], aAh0 + ks * 32);
            LDSM_X4(ah[1][0], ah[1][1], ah[1][2], ah[1][3], aAh1 + ks * 32);
            LDSM_X4(al[0][0], al[0][1], al[0][2], al[0][3], aAl0 + ks * 32);
            LDSM_X4(al[1][0], al[1][1], al[1][2], al[1][3], aAl1 + ks * 32);
            #pragma unroll
            for (int n = 0; n < 2; n++) {
                uint32_t bh0, bh1, bl0, bl1;
                LDSM_X2(bh0, bh1, aBh + n * (8 * LDA * 2) + ks * 32);
                LDSM_X2(bl0, bl1, aBl + n * (8 * LDA * 2) + ks * 32);
                #pragma unroll
                for (int m = 0; m < 2; m++) {
                    MMA16816(acc[m][n], ah[m][0], ah[m][1], ah[m][2], ah[m][3], bh0, bh1);
                    MMA16816(acc[m][n], ah[m][0], ah[m][1], ah[m][2], ah[m][3], bl0, bl1);
                    MMA16816(acc[m][n], al[m][0], al[m][1], al[m][2], al[m][3], bh0, bh1);
                }
            }
        }

        if (Wcls) {
            __syncthreads();
            float* s_h = (float*)(smem + cur * BUF_PAIR);
            #pragma unroll
            for (int n = 0; n < 2; n++) {
                int col = warp_n * 16 + n * 8 + tig * 2;
                float b0 = __ldg(&bvec[col]), b1 = __ldg(&bvec[col + 1]);
                #pragma unroll
                for (int m = 0; m < 2; m++) {
                    int lr0 = warp_m * 32 + m * 16 + gid;
                    int lr1 = lr0 + 8;
                    float f0 = acc[m][n][0] + b0;
                    float f1 = acc[m][n][1] + b1;
                    float f2 = acc[m][n][2] + b0;
                    float f3 = acc[m][n][3] + b1;
                    f0 = f0 >= 0.f ? f0 : SLOPE * f0;
                    f1 = f1 >= 0.f ? f1 : SLOPE * f1;
                    f2 = f2 >= 0.f ? f2 : SLOPE * f2;
                    f3 = f3 >= 0.f ? f3 : SLOPE * f3;
                    s_h[lr0 * 136 + col] = f0; s_h[lr0 * 136 + col + 1] = f1;
                    s_h[lr1 * 136 + col] = f2; s_h[lr1 * 136 + col + 1] = f3;
                }
            }
            __syncthreads();
            float* s_wc = (float*)(smem + OFF_WC);
            int r = tid >> 3;
            int cb = tid & 7;
            float a0 = __ldg(&bcls[cb]);
            #pragma unroll 8
            for (int k = 0; k < HD; k++)
                a0 += s_h[r * 136 + k] * s_wc[k * NC + cb];
            int grow = block_row + r;
            if (grow < NN)
                cls_out[(size_t)grow * NC + cb] = a0;
        } else {
            float on[2][2] = {{1.f, 1.f}, {1.f, 1.f}};
            if (prenorm) {
                #pragma unroll
                for (int m = 0; m < 2; m++) {
                    int r0 = block_row + warp_m * 32 + m * 16 + gid;
                    int r1 = r0 + 8;
                    if (r0 < NN) on[m][0] = __ldg(&prenorm[r0]);
                    if (r1 < NN) on[m][1] = __ldg(&prenorm[r1]);
                }
            }
            #pragma unroll
            for (int n = 0; n < 2; n++) {
                int col = warp_n * 16 + n * 8 + tig * 2;
                float b0 = __ldg(&bvec[col]), b1 = __ldg(&bvec[col + 1]);
                float s1c0 = 0.f, s1c1 = 0.f, s2c0 = 0.f, s2c1 = 0.f;
                #pragma unroll
                for (int m = 0; m < 2; m++) {
                    int r0 = block_row + warp_m * 32 + m * 16 + gid;
                    int r1 = r0 + 8;
                    float f0 = acc[m][n][0] + b0;
                    float f1 = acc[m][n][1] + b1;
                    float f2 = acc[m][n][2] + b0;
                    float f3 = acc[m][n][3] + b1;
                    if (act) {
                        f0 = f0 >= 0.f ? f0 : SLOPE * f0;
                        f1 = f1 >= 0.f ? f1 : SLOPE * f1;
                        f2 = f2 >= 0.f ? f2 : SLOPE * f2;
                        f3 = f3 >= 0.f ? f3 : SLOPE * f3;
                    }
                    if (r0 < NN) {
                        *(__half2*)(out + (size_t)r0 * HD + col) =
                            __floats2half2_rn(f0 * on[m][0], f1 * on[m][0]);
                        s1c0 += f0; s1c1 += f1; s2c0 += f0 * f0; s2c1 += f1 * f1;
                    }
                    if (r1 < NN) {
                        *(__half2*)(out + (size_t)r1 * HD + col) =
                            __floats2half2_rn(f2 * on[m][1], f3 * on[m][1]);
                        s1c0 += f2; s1c1 += f3; s2c0 += f2 * f2; s2c1 += f3 * f3;
                    }
                }
                if (stats) {
                    #pragma unroll
                    for (int o = 4; o <= 16; o <<= 1) {
                        s1c0 += __shfl_xor_sync(0xFFFFFFFFu, s1c0, o);
                        s1c1 += __shfl_xor_sync(0xFFFFFFFFu, s1c1, o);
                        s2c0 += __shfl_xor_sync(0xFFFFFFFFu, s2c0, o);
                        s2c1 += __shfl_xor_sync(0xFFFFFFFFu, s2c1, o);
                    }
                    if (gid == 0) {
                        atomicAdd(&s_stats[col], s1c0);
                        atomicAdd(&s_stats[col + 1], s1c1);
                        atomicAdd(&s_stats[128 + col], s2c0);
                        atomicAdd(&s_stats[128 + col + 1], s2c1);
                    }
                }
            }
        }
        cur ^= 1;
    }

    if (stats) {
        __syncthreads();
        if (tid < 256) atomicAdd(&stats[tid], s_stats[tid]);
    }
}

__global__ void __launch_bounds__(NET_TB, 1)
net_kernel(const int* __restrict__ rowptr, const int* __restrict__ esrc,
           const float* __restrict__ outnorm, const float* __restrict__ innorm,
           const __half* __restrict__ Xh, __half* __restrict__ Bh,
           __nv_bfloat16* __restrict__ Ahi, __nv_bfloat16* __restrict__ Alo,
           const __nv_bfloat16* __restrict__ Wt,
           const float* __restrict__ b1, const float* __restrict__ b2,
           const float* __restrict__ bn1, const float* __restrict__ bn2,
           const float* __restrict__ g1, const float* __restrict__ be1,
           const float* __restrict__ g2, const float* __restrict__ be2,
           float* __restrict__ stats1, float* __restrict__ stats2,
           const float* __restrict__ Wc, const float* __restrict__ bc,
           float* __restrict__ cls_out) {
    extern __shared__ char smem[];
    uint32_t sbase = smem_u32(smem);

    // conv1
    agg_phase(Xh, nullptr, nullptr, nullptr, rowptr, esrc, outnorm, innorm, Ahi, Alo);
    grid_barrier_net(0);
    gemm_phase(smem, sbase, Ahi, Alo, Wt + 0 * 16384, Wt + 1 * 16384,
               b1, Bh, 0, stats1, nullptr, nullptr, nullptr, nullptr);
    grid_barrier_net(1);
    // conv2 (BN1+lrelu fused in gather via stats1)
    agg_phase(Bh, stats1, g1, be1, rowptr, esrc, outnorm, innorm, Ahi, Alo);
    grid_barrier_net(2);
    gemm_phase(smem, sbase, Ahi, Alo, Wt + 2 * 16384, Wt + 3 * 16384,
               b2, Bh, 0, stats2, nullptr, nullptr, nullptr, nullptr);
    grid_barrier_net(3);
    // convnode1 (BN2+lrelu fused; output prescaled by outnorm)
    agg_phase(Bh, stats2, g2, be2, rowptr, esrc, outnorm, innorm, Ahi, Alo);
    grid_barrier_net(4);
    gemm_phase(smem, sbase, Ahi, Alo, Wt + 4 * 16384, Wt + 5 * 16384,
               bn1, Bh, 1, nullptr, outnorm, nullptr, nullptr, nullptr);
    grid_barrier_net(5);
    // convnode2 (input prescaled -> pure sum) + fused classifier
    agg_phase(Bh, nullptr, nullptr, nullptr, rowptr, esrc, outnorm, innorm, Ahi, Alo);
    grid_barrier_net(6);
    gemm_phase(smem, sbase, Ahi, Alo, Wt + 6 * 16384, Wt + 7 * 16384,
               bn2, nullptr, 1, nullptr, nullptr, Wc, bc, cls_out);

    // reset barrier state for graph replay
    __syncthreads();
    if (threadIdx.x == 0) {
        __threadfence();
        unsigned v = atomicAdd(&g_nexit, 1u);
        if (v == NET_GRID - 1) {
            #pragma unroll
            for (int k = 0; k < 8; k++) atomicExch(&g_nbar[k], 0u);
            atomicExch(&g_nexit, 0u);
            __threadfence();
        }
    }
}

// ---------------------------------------------------------------------------
extern "C" void kernel_launch(void* const* d_in, const int* in_sizes, int n_in,
                              void* d_out, int out_size) {
    const float* node_feat = (const float*)d_in[0];
    const int*   src       = (const int*)d_in[1];
    const int*   dst       = (const int*)d_in[2];
    const float* W1  = (const float*)d_in[3];
    const float* b1  = (const float*)d_in[4];
    const float* W2  = (const float*)d_in[5];
    const float* b2  = (const float*)d_in[6];
    const float* g1  = (const float*)d_in[7];
    const float* be1 = (const float*)d_in[8];
    const float* g2  = (const float*)d_in[9];
    const float* be2 = (const float*)d_in[10];
    const float* Wn1 = (const float*)d_in[11];
    const float* bn1 = (const float*)d_in[12];
    const float* Wn2 = (const float*)d_in[13];
    const float* bn2 = (const float*)d_in[14];
    const float* Wc  = (const float*)d_in[15];
    const float* bc  = (const float*)d_in[16];
    float* out = (float*)d_out;

    float *pOutN, *pInN, *pStats1, *pStats2;
    __nv_bfloat16 *pAh, *pAl, *pWt;
    __half *pXh, *pBh;
    int *pSrcC, *pDstC, *pExcl, *pBlk, *pRow, *pCur, *pEsrc;
    cudaGetSymbolAddress((void**)&pAh, g_Ah);
    cudaGetSymbolAddress((void**)&pAl, g_Al);
    cudaGetSymbolAddress((void**)&pXh, g_Xh);
    cudaGetSymbolAddress((void**)&pBh, g_Bh);
    cudaGetSymbolAddress((void**)&pOutN, g_outnorm);
    cudaGetSymbolAddress((void**)&pInN, g_innorm);
    cudaGetSymbolAddress((void**)&pStats1, g_stats1);
    cudaGetSymbolAddress((void**)&pStats2, g_stats2);
    cudaGetSymbolAddress((void**)&pWt, g_Wtb);
    cudaGetSymbolAddress((void**)&pSrcC, g_srccnt);
    cudaGetSymbolAddress((void**)&pDstC, g_dstcnt);
    cudaGetSymbolAddress((void**)&pExcl, g_excl);
    cudaGetSymbolAddress((void**)&pBlk, g_blksum);
    cudaGetSymbolAddress((void**)&pRow, g_rowptr);
    cudaGetSymbolAddress((void**)&pCur, g_cursor);
    cudaGetSymbolAddress((void**)&pEsrc, g_esrc);

    cudaFuncSetAttribute(net_kernel, cudaFuncAttributeMaxDynamicSharedMemorySize, SM_TOTAL);

    // (0) CSR build + norms + stats zero + prescaled Xh
    csr_mega_kernel<<<CSR_GRID, CSR_TB>>>(src, dst, node_feat,
                                          pSrcC, pDstC, pOutN, pInN,
                                          pExcl, pBlk, pRow, pCur, pEsrc,
                                          pXh, pStats1, pStats2);
    // (1) weight prep
    prep_w_kernel<<<4, 256>>>(W1, W2, Wn1, Wn2, pWt);

    // (2) the whole 4-conv network + classifier, one persistent kernel
    net_kernel<<<NET_GRID, NET_TB, SM_TOTAL>>>(pRow, pEsrc, pOutN, pInN,
                                               pXh, pBh, pAh, pAl, pWt,
                                               b1, b2, bn1, bn2,
                                               g1, be1, g2, be2,
                                               pStats1, pStats2,
                                               Wc, bc, out);
}

// round 17
// speedup vs baseline: 1.2918x; 1.2918x over previous
#include <cuda_runtime.h>
#include <cuda_bf16.h>
#include <cuda_fp16.h>
#include <cstdint>

#define NN 100000
#define EE 1600000
#define HD 128
#define NC 8
#define EPS_BN 1e-5f
#define SLOPE 0.01f

#define NTILES ((NN + 127) / 128)                    // 782
#define GEMM_GRID 148
#define GEMM_TB 1024
#define CSR_GRID 148
#define CSR_TB 1024

// padded smem row stride (fp16 elems)
#define LDA 136
#define ABUF_SZ (128 * LDA * 2)             // 34816 (one fp16 A tile)
#define OFF_W_HI (2 * ABUF_SZ)              // 69632
#define OFF_W_LO (OFF_W_HI + ABUF_SZ)       // 104448
#define OFF_STATS (OFF_W_LO + ABUF_SZ)      // 139264
#define OFF_WC   (OFF_STATS + 1024)         // 140288
#define SM_TOTAL (OFF_WC + 4096)            // 144384

// ---- device scratch ----
__device__ __half g_A16[(size_t)NN * HD];   // agg output (fp16)
__device__ __half g_Xh[(size_t)NN * HD];    // fp16 node_feat * outnorm
__device__ __half g_Bh[(size_t)NN * HD];    // fp16 activations
__device__ float g_outnorm[NN];
__device__ float g_innorm[NN];
__device__ int   g_srccnt[NN];
__device__ int   g_dstcnt[NN];
__device__ int   g_excl[NN];
__device__ int   g_blksum[CSR_GRID];
__device__ int   g_rowptr[NN + 1];
__device__ int   g_cursor[NN];
__device__ int   g_esrc[EE];
__device__ float g_stats1[2 * HD];
__device__ float g_stats2[2 * HD];
__device__ float g_scale[HD];
__device__ float g_bias[HD];
__device__ __half g_Wth[8 * 16384];         // 4 weights x {hi,lo} fp16 W^T
__device__ unsigned g_bar[8];
__device__ unsigned g_exit;

// ==================== persistent CSR mega-kernel ============================
__device__ __forceinline__ void grid_barrier(int k) {
    __syncthreads();
    if (threadIdx.x == 0) {
        __threadfence();
        atomicAdd(&g_bar[k], 1u);
        while (atomicAdd(&g_bar[k], 0u) < (unsigned)CSR_GRID) {}
        __threadfence();
    }
    __syncthreads();
}

__global__ void __launch_bounds__(CSR_TB, 1)
csr_mega_kernel(const int* __restrict__ src, const int* __restrict__ dst,
                const float* __restrict__ node_feat,
                int* srccnt, int* dstcnt, float* outnorm, float* innorm,
                int* excl, int* blksum, int* rowptr, int* cursor, int* esrc,
                __half* xh, float* stats1, float* stats2) {
    int tid = threadIdx.x;
    int gtid = blockIdx.x * CSR_TB + tid;
    const int nth = CSR_GRID * CSR_TB;

    for (int i = gtid; i < NN; i += nth) { srccnt[i] = 0; dstcnt[i] = 0; }
    if (gtid < 2 * HD) { stats1[gtid] = 0.f; stats2[gtid] = 0.f; }
    grid_barrier(0);

    for (int e = gtid; e < EE; e += nth) {
        atomicAdd(&srccnt[src[e]], 1);
        atomicAdd(&dstcnt[dst[e]], 1);
    }
    grid_barrier(1);

    for (int i = gtid; i < NN; i += nth) {
        outnorm[i] = rsqrtf(fmaxf((float)srccnt[i], 1.f));
        innorm[i]  = rsqrtf(fmaxf((float)dstcnt[i], 1.f));
    }
    {
        __shared__ int sh[CSR_TB];
        int i = gtid;
        int v = (i < NN) ? dstcnt[i] : 0;
        sh[tid] = v;
        __syncthreads();
        for (int off = 1; off < CSR_TB; off <<= 1) {
            int t = (tid >= off) ? sh[tid - off] : 0;
            __syncthreads();
            sh[tid] += t;
            __syncthreads();
        }
        if (i < NN) excl[i] = sh[tid] - v;
        if (tid == CSR_TB - 1) blksum[blockIdx.x] = sh[tid];
    }
    grid_barrier(2);

    if (blockIdx.x == 0) {
        __shared__ int sb2[256];
        int v = (tid < CSR_GRID) ? blksum[tid] : 0;
        if (tid < 256) sb2[tid] = v;
        __syncthreads();
        for (int off = 1; off < 256; off <<= 1) {
            int t = (tid >= off && tid < 256) ? sb2[tid - off] : 0;
            __syncthreads();
            if (tid < 256) sb2[tid] += t;
            __syncthreads();
        }
        if (tid < CSR_GRID) blksum[tid] = sb2[tid] - v;
    }
    grid_barrier(3);

    for (int i = gtid; i < NN; i += nth) {
        int r = excl[i] + blksum[i >> 10];
        rowptr[i] = r;
        cursor[i] = r;
    }
    for (long long i = gtid; i < (long long)NN * 64; i += nth) {
        int node = (int)(i >> 6);
        float w = outnorm[node];
        float2 v = ((const float2*)node_feat)[i];
        ((__half2*)xh)[i] = __floats2half2_rn(v.x * w, v.y * w);
    }
    if (gtid == 0) rowptr[NN] = EE;
    grid_barrier(4);

    for (int e = gtid; e < EE; e += nth) {
        int p = atomicAdd(&cursor[dst[e]], 1);
        esrc[p] = src[e];
    }

    __syncthreads();
    if (tid == 0) {
        __threadfence();
        unsigned v = atomicAdd(&g_exit, 1u);
        if (v == CSR_GRID - 1) {
            #pragma unroll
            for (int k = 0; k < 8; k++) atomicExch(&g_bar[k], 0u);
            atomicExch(&g_exit, 0u);
            __threadfence();
        }
    }
}

// ============================ aggregation ===================================
// One warp per node (R11/R15-proven). Output: single fp16 buffer.
__global__ void agg_kernel(const __half* __restrict__ x,
                           const int* __restrict__ rowptr,
                           const int* __restrict__ esrc,
                           const float* __restrict__ outnorm,
                           const float* __restrict__ innorm,
                           __half* __restrict__ A16,
                           const float* __restrict__ scale,
                           const float* __restrict__ bias) {
    int warp = (blockIdx.x * blockDim.x + threadIdx.x) >> 5;
    if (warp >= NN) return;
    int lane = threadIdx.x & 31;
    int beg = rowptr[warp], end = rowptr[warp + 1];
    const uint2* x2 = (const uint2*)x;
    float4 acc = make_float4(0.f, 0.f, 0.f, 0.f);

    if (scale) {
        float4 sc = ((const float4*)scale)[lane];
        float4 bi = ((const float4*)bias)[lane];
        int j = beg;
        for (; j + 1 < end; j += 2) {
            int s0 = esrc[j], s1 = esrc[j + 1];
            float w0 = outnorm[s0], w1 = outnorm[s1];
            uint2 u0 = x2[(size_t)s0 * 32 + lane];
            uint2 u1 = x2[(size_t)s1 * 32 + lane];
            float2 a0 = __half22float2(*(__half2*)&u0.x);
            float2 a1 = __half22float2(*(__half2*)&u0.y);
            float2 c0 = __half22float2(*(__half2*)&u1.x);
            float2 c1 = __half22float2(*(__half2*)&u1.y);
            float t0, t1;
            t0 = fmaf(a0.x, sc.x, bi.x); t0 = t0 >= 0.f ? t0 : SLOPE * t0;
            t1 = fmaf(c0.x, sc.x, bi.x); t1 = t1 >= 0.f ? t1 : SLOPE * t1;
            acc.x += w0 * t0 + w1 * t1;
            t0 = fmaf(a0.y, sc.y, bi.y); t0 = t0 >= 0.f ? t0 : SLOPE * t0;
            t1 = fmaf(c0.y, sc.y, bi.y); t1 = t1 >= 0.f ? t1 : SLOPE * t1;
            acc.y += w0 * t0 + w1 * t1;
            t0 = fmaf(a1.x, sc.z, bi.z); t0 = t0 >= 0.f ? t0 : SLOPE * t0;
            t1 = fmaf(c1.x, sc.z, bi.z); t1 = t1 >= 0.f ? t1 : SLOPE * t1;
            acc.z += w0 * t0 + w1 * t1;
            t0 = fmaf(a1.y, sc.w, bi.w); t0 = t0 >= 0.f ? t0 : SLOPE * t0;
            t1 = fmaf(c1.y, sc.w, bi.w); t1 = t1 >= 0.f ? t1 : SLOPE * t1;
            acc.w += w0 * t0 + w1 * t1;
        }
        if (j < end) {
            int s = esrc[j];
            float w = outnorm[s];
            uint2 u = x2[(size_t)s * 32 + lane];
            float2 a0 = __half22float2(*(__half2*)&u.x);
            float2 a1 = __half22float2(*(__half2*)&u.y);
            float t;
            t = fmaf(a0.x, sc.x, bi.x); t = t >= 0.f ? t : SLOPE * t; acc.x += w * t;
            t = fmaf(a0.y, sc.y, bi.y); t = t >= 0.f ? t : SLOPE * t; acc.y += w * t;
            t = fmaf(a1.x, sc.z, bi.z); t = t >= 0.f ? t : SLOPE * t; acc.z += w * t;
            t = fmaf(a1.y, sc.w, bi.w); t = t >= 0.f ? t : SLOPE * t; acc.w += w * t;
        }
    } else {
        int j = beg;
        for (; j + 3 < end; j += 4) {
            int s0 = esrc[j], s1 = esrc[j + 1], s2 = esrc[j + 2], s3 = esrc[j + 3];
            uint2 u0 = x2[(size_t)s0 * 32 + lane];
            uint2 u1 = x2[(size_t)s1 * 32 + lane];
            uint2 u2 = x2[(size_t)s2 * 32 + lane];
            uint2 u3 = x2[(size_t)s3 * 32 + lane];
            float2 a0 = __half22float2(*(__half2*)&u0.x), a1 = __half22float2(*(__half2*)&u0.y);
            float2 b0 = __half22float2(*(__half2*)&u1.x), b1 = __half22float2(*(__half2*)&u1.y);
            float2 c0 = __half22float2(*(__half2*)&u2.x), c1 = __half22float2(*(__half2*)&u2.y);
            float2 d0 = __half22float2(*(__half2*)&u3.x), d1 = __half22float2(*(__half2*)&u3.y);
            acc.x += a0.x + b0.x + c0.x + d0.x;
            acc.y += a0.y + b0.y + c0.y + d0.y;
            acc.z += a1.x + b1.x + c1.x + d1.x;
            acc.w += a1.y + b1.y + c1.y + d1.y;
        }
        for (; j < end; j++) {
            int s = esrc[j];
            uint2 u = x2[(size_t)s * 32 + lane];
            float2 a0 = __half22float2(*(__half2*)&u.x);
            float2 a1 = __half22float2(*(__half2*)&u.y);
            acc.x += a0.x; acc.y += a0.y; acc.z += a1.x; acc.w += a1.y;
        }
    }
    float in = innorm[warp];
    __half2 p0 = __floats2half2_rn(acc.x * in, acc.y * in);
    __half2 p1 = __floats2half2_rn(acc.z * in, acc.w * in);
    ((uint2*)(A16 + (size_t)warp * HD))[lane] = make_uint2(*(uint32_t*)&p0, *(uint32_t*)&p1);
}

// ===================== weight prep: W^T hi/lo fp16 ==========================
__global__ void prep_w_kernel(const float* __restrict__ Wa, const float* __restrict__ Wb,
                              const float* __restrict__ Wc_, const float* __restrict__ Wd,
                              __half* __restrict__ Wt) {
    const float* W = (blockIdx.x == 0) ? Wa : (blockIdx.x == 1) ? Wb : (blockIdx.x == 2) ? Wc_ : Wd;
    __half* hi_t = Wt + (size_t)blockIdx.x * 2 * 16384;
    __half* lo_t = hi_t + 16384;
    for (int idx = threadIdx.x; idx < HD * HD; idx += 256) {
        int k = idx >> 7, n = idx & 127;
        float w = W[idx];
        __half h = __float2half_rn(w);
        float r = w - __half2float(h);
        hi_t[n * HD + k] = h;
        lo_t[n * HD + k] = __float2half_rn(r);
    }
}

// ====== persistent pipelined mma.sync f16 2-pass GEMM (1024 thr, 32 warps) ==
__device__ __forceinline__ uint32_t smem_u32(const void* p) {
    uint32_t a;
    asm("{ .reg .u64 t; cvta.to.shared.u64 t, %1; cvt.u32.u64 %0, t; }" : "=r"(a) : "l"(p));
    return a;
}
#define LDSM_X4(r0, r1, r2, r3, a) \
    asm volatile("ldmatrix.sync.aligned.m8n8.x4.shared.b16 {%0,%1,%2,%3}, [%4];" \
        : "=r"(r0), "=r"(r1), "=r"(r2), "=r"(r3) : "r"(a))
#define LDSM_X2(r0, r1, a) \
    asm volatile("ldmatrix.sync.aligned.m8n8.x2.shared.b16 {%0,%1}, [%2];" \
        : "=r"(r0), "=r"(r1) : "r"(a))
#define MMA16816F(c, A0, A1, A2, A3, B0, B1) \
    asm volatile("mma.sync.aligned.m16n8k16.row.col.f32.f16.f16.f32 " \
        "{%0,%1,%2,%3}, {%4,%5,%6,%7}, {%8,%9}, {%0,%1,%2,%3};" \
        : "+f"((c)[0]), "+f"((c)[1]), "+f"((c)[2]), "+f"((c)[3]) \
        : "r"(A0), "r"(A1), "r"(A2), "r"(A3), "r"(B0), "r"(B1))
#define CP_ASYNC16(dst, src, sz) \
    asm volatile("cp.async.cg.shared.global [%0], [%1], 16, %2;" :: "r"(dst), "l"(src), "r"(sz))
#define CP_COMMIT() asm volatile("cp.async.commit_group;" ::: "memory")
#define CP_WAIT0()  asm volatile("cp.async.wait_group 0;" ::: "memory")

__global__ void __launch_bounds__(GEMM_TB, 1)
gemm_mma_kernel(const __half* __restrict__ A16,
                const __half* __restrict__ Wt_hi,
                const __half* __restrict__ Wt_lo,
                const float* __restrict__ bvec,
                __half* __restrict__ out, int act,
                float* __restrict__ stats,
                const float* __restrict__ prenorm,
                const float* __restrict__ Wcls,
                const float* __restrict__ bcls,
                float* __restrict__ cls_out) {
    extern __shared__ char smem[];
    uint32_t sbase = smem_u32(smem);
    float* s_stats = (float*)(smem + OFF_STATS);
    int tid = threadIdx.x;
    int wid = tid >> 5;
    int lane = tid & 31;

    {
        const uint32_t* wh = (const uint32_t*)Wt_hi;
        const uint32_t* wl = (const uint32_t*)Wt_lo;
        #pragma unroll
        for (int i = tid; i < 8192; i += GEMM_TB) {
            int n = i >> 6, kp = i & 63;
            *(uint32_t*)(smem + OFF_W_HI + n * (LDA * 2) + kp * 4) = wh[i];
            *(uint32_t*)(smem + OFF_W_LO + n * (LDA * 2) + kp * 4) = wl[i];
        }
    }
    if (stats && tid < 256) s_stats[tid] = 0.f;
    if (Wcls) {
        float* s_wc = (float*)(smem + OFF_WC);
        for (int i = tid; i < HD * NC; i += GEMM_TB) s_wc[i] = __ldg(&Wcls[i]);
    }

    // 32 warps: 4m x 8n ; each warp 32 rows x 16 cols
    int warp_m = wid >> 3;
    int warp_n = wid & 7;
    int sub = lane >> 3, r8 = lane & 7;
    int arow = warp_m * 32 + (sub & 1) * 8 + r8;
    int akoff = (sub >> 1) * 8;
    uint32_t relA0 = (uint32_t)(arow * LDA + akoff) * 2;
    uint32_t relA1 = relA0 + 16 * LDA * 2;
    int bl = lane & 15;
    int brow = warp_n * 16 + (bl & 7);
    int bkoff = (bl >> 3) * 8;
    uint32_t aBh = sbase + OFF_W_HI + (brow * LDA + bkoff) * 2;
    uint32_t aBl = aBh + (OFF_W_LO - OFF_W_HI);
    int gid = lane >> 2, tig = lane & 3;

    // prefetch: 1024 threads, 8 per row; each 2x16B (row = 256B)
    int pr = tid >> 3;
    int pq = tid & 7;
    uint32_t pdst_rel = (uint32_t)(pr * LDA + pq * 16) * 2;

    {
        int grow = blockIdx.x * 128 + pr;
        uint32_t sz = (grow < NN) ? 16u : 0u;
        const char* sa = (const char*)(A16 + (size_t)grow * HD + pq * 16);
        uint32_t da = sbase + pdst_rel;
        CP_ASYNC16(da, sa, sz);
        CP_ASYNC16(da + 16, sa + 16, sz);
    }
    CP_COMMIT();
    __syncthreads();

    int cur = 0;
    for (int tile = blockIdx.x; tile < NTILES; tile += GEMM_GRID) {
        int block_row = tile * 128;
        int next = tile + GEMM_GRID;

        CP_WAIT0();
        __syncthreads();

        if (next < NTILES) {
            int grow = next * 128 + pr;
            uint32_t sz = (grow < NN) ? 16u : 0u;
            const char* sa = (const char*)(A16 + (size_t)grow * HD + pq * 16);
            uint32_t da = sbase + (cur ^ 1) * ABUF_SZ + pdst_rel;
            CP_ASYNC16(da, sa, sz);
            CP_ASYNC16(da + 16, sa + 16, sz);
        }
        CP_COMMIT();

        uint32_t bufb = sbase + cur * ABUF_SZ;
        uint32_t aA0 = bufb + relA0;
        uint32_t aA1 = bufb + relA1;

        float acc[2][2][4];
        #pragma unroll
        for (int m = 0; m < 2; m++)
            #pragma unroll
            for (int n = 0; n < 2; n++)
                #pragma unroll
                for (int q = 0; q < 4; q++) acc[m][n][q] = 0.f;

        #pragma unroll
        for (int ks = 0; ks < 8; ks++) {
            uint32_t a[2][4];
            LDSM_X4(a[0][0], a[0][1], a[0][2], a[0][3], aA0 + ks * 32);
            LDSM_X4(a[1][0], a[1][1], a[1][2], a[1][3], aA1 + ks * 32);
            #pragma unroll
            for (int n = 0; n < 2; n++) {
                uint32_t bh0, bh1, bl0, bl1;
                LDSM_X2(bh0, bh1, aBh + n * (8 * LDA * 2) + ks * 32);
                LDSM_X2(bl0, bl1, aBl + n * (8 * LDA * 2) + ks * 32);
                #pragma unroll
                for (int m = 0; m < 2; m++) {
                    MMA16816F(acc[m][n], a[m][0], a[m][1], a[m][2], a[m][3], bh0, bh1);
                    MMA16816F(acc[m][n], a[m][0], a[m][1], a[m][2], a[m][3], bl0, bl1);
                }
            }
        }

        if (Wcls) {
            // classifier: h tile (fp16) into the dead current A buffer
            __syncthreads();
            __half* s_h = (__half*)(smem + cur * ABUF_SZ);
            #pragma unroll
            for (int n = 0; n < 2; n++) {
                int col = warp_n * 16 + n * 8 + tig * 2;
                float b0 = __ldg(&bvec[col]), b1 = __ldg(&bvec[col + 1]);
                #pragma unroll
                for (int m = 0; m < 2; m++) {
                    int lr0 = warp_m * 32 + m * 16 + gid;
                    int lr1 = lr0 + 8;
                    float f0 = acc[m][n][0] + b0;
                    float f1 = acc[m][n][1] + b1;
                    float f2 = acc[m][n][2] + b0;
                    float f3 = acc[m][n][3] + b1;
                    f0 = f0 >= 0.f ? f0 : SLOPE * f0;
                    f1 = f1 >= 0.f ? f1 : SLOPE * f1;
                    f2 = f2 >= 0.f ? f2 : SLOPE * f2;
                    f3 = f3 >= 0.f ? f3 : SLOPE * f3;
                    *(__half2*)(s_h + lr0 * LDA + col) = __floats2half2_rn(f0, f1);
                    *(__half2*)(s_h + lr1 * LDA + col) = __floats2half2_rn(f2, f3);
                }
            }
            __syncthreads();
            float* s_wc = (float*)(smem + OFF_WC);
            int r = tid >> 3;
            int cb = tid & 7;
            float a0 = __ldg(&bcls[cb]);
            #pragma unroll 8
            for (int k = 0; k < HD; k++)
                a0 += __half2float(s_h[r * LDA + k]) * s_wc[k * NC + cb];
            int grow = block_row + r;
            if (grow < NN)
                cls_out[(size_t)grow * NC + cb] = a0;
        } else {
            float on[2][2] = {{1.f, 1.f}, {1.f, 1.f}};
            if (prenorm) {
                #pragma unroll
                for (int m = 0; m < 2; m++) {
                    int r0 = block_row + warp_m * 32 + m * 16 + gid;
                    int r1 = r0 + 8;
                    if (r0 < NN) on[m][0] = __ldg(&prenorm[r0]);
                    if (r1 < NN) on[m][1] = __ldg(&prenorm[r1]);
                }
            }
            #pragma unroll
            for (int n = 0; n < 2; n++) {
                int col = warp_n * 16 + n * 8 + tig * 2;
                float b0 = __ldg(&bvec[col]), b1 = __ldg(&bvec[col + 1]);
                float s1c0 = 0.f, s1c1 = 0.f, s2c0 = 0.f, s2c1 = 0.f;
                #pragma unroll
                for (int m = 0; m < 2; m++) {
                    int r0 = block_row + warp_m * 32 + m * 16 + gid;
                    int r1 = r0 + 8;
                    float f0 = acc[m][n][0] + b0;
                    float f1 = acc[m][n][1] + b1;
                    float f2 = acc[m][n][2] + b0;
                    float f3 = acc[m][n][3] + b1;
                    if (act) {
                        f0 = f0 >= 0.f ? f0 : SLOPE * f0;
                        f1 = f1 >= 0.f ? f1 : SLOPE * f1;
                        f2 = f2 >= 0.f ? f2 : SLOPE * f2;
                        f3 = f3 >= 0.f ? f3 : SLOPE * f3;
                    }
                    if (r0 < NN) {
                        *(__half2*)(out + (size_t)r0 * HD + col) =
                            __floats2half2_rn(f0 * on[m][0], f1 * on[m][0]);
                        s1c0 += f0; s1c1 += f1; s2c0 += f0 * f0; s2c1 += f1 * f1;
                    }
                    if (r1 < NN) {
                        *(__half2*)(out + (size_t)r1 * HD + col) =
                            __floats2half2_rn(f2 * on[m][1], f3 * on[m][1]);
                        s1c0 += f2; s1c1 += f3; s2c0 += f2 * f2; s2c1 += f3 * f3;
                    }
                }
                if (stats) {
                    #pragma unroll
                    for (int o = 4; o <= 16; o <<= 1) {
                        s1c0 += __shfl_xor_sync(0xFFFFFFFFu, s1c0, o);
                        s1c1 += __shfl_xor_sync(0xFFFFFFFFu, s1c1, o);
                        s2c0 += __shfl_xor_sync(0xFFFFFFFFu, s2c0, o);
                        s2c1 += __shfl_xor_sync(0xFFFFFFFFu, s2c1, o);
                    }
                    if (gid == 0) {
                        atomicAdd(&s_stats[col], s1c0);
                        atomicAdd(&s_stats[col + 1], s1c1);
                        atomicAdd(&s_stats[128 + col], s2c0);
                        atomicAdd(&s_stats[128 + col + 1], s2c1);
                    }
                }
            }
        }
        cur ^= 1;
    }

    if (stats) {
        __syncthreads();
        if (tid < 256) atomicAdd(&stats[tid], s_stats[tid]);
    }
}

// scale/bias from BN stats
__global__ void sb_kernel(const float* __restrict__ stats,
                          const float* __restrict__ gamma,
                          const float* __restrict__ beta,
                          float* __restrict__ scale, float* __restrict__ bias) {
    int c = threadIdx.x;
    float mean = stats[c] * (1.f / NN);
    float var = stats[HD + c] * (1.f / NN) - mean * mean;
    float r = rsqrtf(var + EPS_BN) * gamma[c];
    scale[c] = r;
    bias[c] = beta[c] - mean * r;
}

// ---------------------------------------------------------------------------
extern "C" void kernel_launch(void* const* d_in, const int* in_sizes, int n_in,
                              void* d_out, int out_size) {
    const float* node_feat = (const float*)d_in[0];
    const int*   src       = (const int*)d_in[1];
    const int*   dst       = (const int*)d_in[2];
    const float* W1  = (const float*)d_in[3];
    const float* b1  = (const float*)d_in[4];
    const float* W2  = (const float*)d_in[5];
    const float* b2  = (const float*)d_in[6];
    const float* g1  = (const float*)d_in[7];
    const float* be1 = (const float*)d_in[8];
    const float* g2  = (const float*)d_in[9];
    const float* be2 = (const float*)d_in[10];
    const float* Wn1 = (const float*)d_in[11];
    const float* bn1 = (const float*)d_in[12];
    const float* Wn2 = (const float*)d_in[13];
    const float* bn2 = (const float*)d_in[14];
    const float* Wc  = (const float*)d_in[15];
    const float* bc  = (const float*)d_in[16];
    float* out = (float*)d_out;

    float *pOutN, *pInN, *pStats1, *pStats2, *pScale, *pBias;
    __half *pA16, *pXh, *pBh, *pWt;
    int *pSrcC, *pDstC, *pExcl, *pBlk, *pRow, *pCur, *pEsrc;
    cudaGetSymbolAddress((void**)&pA16, g_A16);
    cudaGetSymbolAddress((void**)&pXh, g_Xh);
    cudaGetSymbolAddress((void**)&pBh, g_Bh);
    cudaGetSymbolAddress((void**)&pOutN, g_outnorm);
    cudaGetSymbolAddress((void**)&pInN, g_innorm);
    cudaGetSymbolAddress((void**)&pStats1, g_stats1);
    cudaGetSymbolAddress((void**)&pStats2, g_stats2);
    cudaGetSymbolAddress((void**)&pWt, g_Wth);
    cudaGetSymbolAddress((void**)&pScale, g_scale);
    cudaGetSymbolAddress((void**)&pBias, g_bias);
    cudaGetSymbolAddress((void**)&pSrcC, g_srccnt);
    cudaGetSymbolAddress((void**)&pDstC, g_dstcnt);
    cudaGetSymbolAddress((void**)&pExcl, g_excl);
    cudaGetSymbolAddress((void**)&pBlk, g_blksum);
    cudaGetSymbolAddress((void**)&pRow, g_rowptr);
    cudaGetSymbolAddress((void**)&pCur, g_cursor);
    cudaGetSymbolAddress((void**)&pEsrc, g_esrc);

    cudaFuncSetAttribute(gemm_mma_kernel, cudaFuncAttributeMaxDynamicSharedMemorySize, SM_TOTAL);

    const int TB = 256;
    const int gridAggW = (NN * 32 + TB - 1) / TB;

    // (0) CSR build + norms + stats zero + prescaled Xh
    csr_mega_kernel<<<CSR_GRID, CSR_TB>>>(src, dst, node_feat,
                                          pSrcC, pDstC, pOutN, pInN,
                                          pExcl, pBlk, pRow, pCur, pEsrc,
                                          pXh, pStats1, pStats2);
    // (1) weight prep
    prep_w_kernel<<<4, TB>>>(W1, W2, Wn1, Wn2, pWt);

    // (2) conv1 agg
    agg_kernel<<<gridAggW, TB>>>(pXh, pRow, pEsrc, pOutN, pInN, pA16, nullptr, nullptr);
    // (3) conv1 gemm (+stats1)  <-- ncu capture target
    gemm_mma_kernel<<<GEMM_GRID, GEMM_TB, SM_TOTAL>>>(pA16, pWt + 0 * 16384, pWt + 1 * 16384,
        b1, pBh, 0, pStats1, nullptr, nullptr, nullptr, nullptr);
    // (4) BN1 scale/bias
    sb_kernel<<<1, 128>>>(pStats1, g1, be1, pScale, pBias);

    // (5)(6)(7) conv2
    agg_kernel<<<gridAggW, TB>>>(pBh, pRow, pEsrc, pOutN, pInN, pA16, pScale, pBias);
    gemm_mma_kernel<<<GEMM_GRID, GEMM_TB, SM_TOTAL>>>(pA16, pWt + 2 * 16384, pWt + 3 * 16384,
        b2, pBh, 0, pStats2, nullptr, nullptr, nullptr, nullptr);
    sb_kernel<<<1, 128>>>(pStats2, g2, be2, pScale, pBias);

    // (8)(9) convnode1 (output prescaled by outnorm)
    agg_kernel<<<gridAggW, TB>>>(pBh, pRow, pEsrc, pOutN, pInN, pA16, pScale, pBias);
    gemm_mma_kernel<<<GEMM_GRID, GEMM_TB, SM_TOTAL>>>(pA16, pWt + 4 * 16384, pWt + 5 * 16384,
        bn1, pBh, 1, nullptr, pOutN, nullptr, nullptr, nullptr);

    // (10)(11) convnode2 + fused classifier -> d_out
    agg_kernel<<<gridAggW, TB>>>(pBh, pRow, pEsrc, pOutN, pInN, pA16, nullptr, nullptr);
    gemm_mma_kernel<<<GEMM_GRID, GEMM_TB, SM_TOTAL>>>(pA16, pWt + 6 * 16384, pWt + 7 * 16384,
        bn2, nullptr, 1, nullptr, nullptr, Wc, bc, out);
}